// round 16
// baseline (speedup 1.0000x reference)
#include <cuda_runtime.h>
#include <cuda_bf16.h>
#include <cstdint>

// Problem constants
#define SEQ     4096
#define DMODEL  1024
#define NHEADS  16
#define HD      64
#define WINDOW  256

// ---------------- scratch (no allocation allowed) ----------------
__device__ float g_q[SEQ * DMODEL];
__device__ float g_k[SEQ * DMODEL];
__device__ float g_v[SEQ * DMODEL];
__device__ float g_att[SEQ * DMODEL];

// ================= split-bf16 tensor-core GEMM via mma.sync =================
// C[4096,1024] = A[4096,1024] @ W[1024,1024] + bias
// 128x128 tile/CTA, 256 threads (8 warps, 2x4), K chunks of 32.
// Each fp32 operand split into bf16 hi + bf16 lo residual; 3 MMAs per tile
// (hi*hi + hi*lo + lo*hi) with fp32 accumulation => fp32-class accuracy.

#define KPAD 40   // halves per smem row (80B): 20*row mod 32 = perfect bank perm
// XOR swizzle (bits >=3 only, preserves pairs/quads) to break store conflicts
#define KSW(row, k) ((k) ^ (8 * (((row) >> 3) & 3)))

__device__ __forceinline__ void split_bf(float x, uint16_t& h, uint16_t& l) {
    __nv_bfloat16 hb = __float2bfloat16(x);
    float r = x - __bfloat162float(hb);
    __nv_bfloat16 lb = __float2bfloat16(r);
    h = reinterpret_cast<unsigned short&>(hb);
    l = reinterpret_cast<unsigned short&>(lb);
}

#define MMA_BF16(d, a, b)                                                      \
    asm volatile(                                                              \
        "mma.sync.aligned.m16n8k16.row.col.f32.bf16.bf16.f32 "                 \
        "{%0,%1,%2,%3}, {%4,%5,%6,%7}, {%8,%9}, {%0,%1,%2,%3};"                \
        : "+f"((d)[0]), "+f"((d)[1]), "+f"((d)[2]), "+f"((d)[3])               \
        : "r"((a)[0]), "r"((a)[1]), "r"((a)[2]), "r"((a)[3]),                  \
          "r"((b)[0]), "r"((b)[1]))

__global__ __launch_bounds__(256) void gemm_mma(
    const float* __restrict__ A, const float* __restrict__ W,
    const float* __restrict__ bias, float* __restrict__ C)
{
    __shared__ __align__(16) uint16_t Ahi[128][KPAD];
    __shared__ __align__(16) uint16_t Alo[128][KPAD];
    __shared__ __align__(16) uint16_t Bhi[128][KPAD];
    __shared__ __align__(16) uint16_t Blo[128][KPAD];

    const int tid  = threadIdx.x;
    const int lane = tid & 31;
    const int wid  = tid >> 5;
    const int mw = (wid >> 2) * 64;    // warp m offset within tile
    const int nw = (wid & 3) * 32;     // warp n offset within tile
    const int r  = lane >> 2;          // 0..7
    const int cq = (lane & 3) * 2;     // 0,2,4,6
    const int m0 = blockIdx.y * 128, n0 = blockIdx.x * 128;

    float acc[4][4][4];
#pragma unroll
    for (int mt = 0; mt < 4; mt++)
#pragma unroll
        for (int nt = 0; nt < 4; nt++)
#pragma unroll
            for (int e = 0; e < 4; e++) acc[mt][nt][e] = 0.0f;

    for (int ch = 0; ch < DMODEL / 32; ch++) {
        // ---- stage A chunk: 128 rows x 32 k, split to hi/lo bf16 ----
#pragma unroll
        for (int it = 0; it < 4; it++) {
            int f = it * 256 + tid;          // 0..1023
            int m = f >> 3;                  // 0..127
            int kf = (f & 7) * 4;            // 0..28
            float4 av = *(const float4*)&A[(size_t)(m0 + m) * DMODEL + ch * 32 + kf];
            uint16_t h0, l0, h1, l1, h2, l2, h3, l3;
            split_bf(av.x, h0, l0); split_bf(av.y, h1, l1);
            split_bf(av.z, h2, l2); split_bf(av.w, h3, l3);
            int k0 = KSW(m, kf);
            uint32_t* ah = (uint32_t*)&Ahi[m][k0];
            uint32_t* al = (uint32_t*)&Alo[m][k0];
            ah[0] = (uint32_t)h0 | ((uint32_t)h1 << 16);
            ah[1] = (uint32_t)h2 | ((uint32_t)h3 << 16);
            al[0] = (uint32_t)l0 | ((uint32_t)l1 << 16);
            al[1] = (uint32_t)l2 | ((uint32_t)l3 << 16);
        }
        // ---- stage B chunk: W[k, n0..n0+127] -> Bs[n][k] (n per thread) ----
#pragma unroll
        for (int it = 0; it < 4; it++) {
            int f = it * 256 + tid;          // 0..1023
            int n = f & 127;
            int kf = (f >> 7) * 4;           // 0..28
            const float* wp = &W[(size_t)(ch * 32 + kf) * DMODEL + n0 + n];
            float w0 = wp[0];
            float w1 = wp[DMODEL];
            float w2 = wp[2 * DMODEL];
            float w3 = wp[3 * DMODEL];
            uint16_t h0, l0, h1, l1, h2, l2, h3, l3;
            split_bf(w0, h0, l0); split_bf(w1, h1, l1);
            split_bf(w2, h2, l2); split_bf(w3, h3, l3);
            int k0 = KSW(n, kf);
            uint32_t* bh = (uint32_t*)&Bhi[n][k0];
            uint32_t* bl = (uint32_t*)&Blo[n][k0];
            bh[0] = (uint32_t)h0 | ((uint32_t)h1 << 16);
            bh[1] = (uint32_t)h2 | ((uint32_t)h3 << 16);
            bl[0] = (uint32_t)l0 | ((uint32_t)l1 << 16);
            bl[1] = (uint32_t)l2 | ((uint32_t)l3 << 16);
        }
        __syncthreads();

        // ---- compute: 2 k-steps of 16 ----
#pragma unroll
        for (int kk = 0; kk < 32; kk += 16) {
            uint32_t ah[4][4], al[4][4], bh[4][2], bl[4][2];
#pragma unroll
            for (int mt = 0; mt < 4; mt++) {
                int row0 = mw + mt * 16 + r;
                int row1 = row0 + 8;
                int ka0  = KSW(row0, kk + cq);
                int ka0b = KSW(row0, kk + cq + 8);
                int ka1  = KSW(row1, kk + cq);
                int ka1b = KSW(row1, kk + cq + 8);
                ah[mt][0] = *(const uint32_t*)&Ahi[row0][ka0];
                ah[mt][1] = *(const uint32_t*)&Ahi[row1][ka1];
                ah[mt][2] = *(const uint32_t*)&Ahi[row0][ka0b];
                ah[mt][3] = *(const uint32_t*)&Ahi[row1][ka1b];
                al[mt][0] = *(const uint32_t*)&Alo[row0][ka0];
                al[mt][1] = *(const uint32_t*)&Alo[row1][ka1];
                al[mt][2] = *(const uint32_t*)&Alo[row0][ka0b];
                al[mt][3] = *(const uint32_t*)&Alo[row1][ka1b];
            }
#pragma unroll
            for (int nt = 0; nt < 4; nt++) {
                int n = nw + nt * 8 + r;
                int kb0 = KSW(n, kk + cq);
                int kb1 = KSW(n, kk + cq + 8);
                bh[nt][0] = *(const uint32_t*)&Bhi[n][kb0];
                bh[nt][1] = *(const uint32_t*)&Bhi[n][kb1];
                bl[nt][0] = *(const uint32_t*)&Blo[n][kb0];
                bl[nt][1] = *(const uint32_t*)&Blo[n][kb1];
            }
#pragma unroll
            for (int mt = 0; mt < 4; mt++)
#pragma unroll
                for (int nt = 0; nt < 4; nt++) {
                    MMA_BF16(acc[mt][nt], ah[mt], bh[nt]);
                    MMA_BF16(acc[mt][nt], ah[mt], bl[nt]);
                    MMA_BF16(acc[mt][nt], al[mt], bh[nt]);
                }
        }
        __syncthreads();
    }

    // ---- epilogue: registers -> C with bias ----
#pragma unroll
    for (int nt = 0; nt < 4; nt++) {
        int col = n0 + nw + nt * 8 + cq;
        float b0 = __ldg(&bias[col]);
        float b1 = __ldg(&bias[col + 1]);
#pragma unroll
        for (int mt = 0; mt < 4; mt++) {
            int row0 = m0 + mw + mt * 16 + r;
            float2 o0 = make_float2(acc[mt][nt][0] + b0, acc[mt][nt][1] + b1);
            float2 o1 = make_float2(acc[mt][nt][2] + b0, acc[mt][nt][3] + b1);
            *(float2*)&C[(size_t)row0 * DMODEL + col] = o0;
            *(float2*)&C[(size_t)(row0 + 8) * DMODEL + col] = o1;
        }
    }
}

// ---------------- sliding-window flash attention (fp32) ----------------
#define ATT_SMEM_FLOATS (64*64 + 64*68 + 64*64 + 64*68)

__global__ __launch_bounds__(256) void attn_kernel(
    const float* __restrict__ q, const float* __restrict__ k,
    const float* __restrict__ v, float* __restrict__ o)
{
    extern __shared__ float sm[];
    float* Qs = sm;                 // [64][64]
    float* Kt = Qs + 64 * 64;       // [64][68] d-major
    float* Vs = Kt + 64 * 68;       // [64][64]
    float* Ps = Vs + 64 * 64;       // [64][68] c-major

    const int tid = threadIdx.x;
    const int tx = tid & 15;
    const int ty = tid >> 4;
    const int qb = blockIdx.x;
    const int hoff = blockIdx.y * HD;

#pragma unroll
    for (int t = 0; t < 4; t++) {
        int f = t * 256 + tid;
        int r = f >> 4, dq = f & 15;
        float4 qv = *(const float4*)&q[(size_t)(qb * 64 + r) * DMODEL + hoff + dq * 4];
        qv.x *= 0.125f; qv.y *= 0.125f; qv.z *= 0.125f; qv.w *= 0.125f;
        *(float4*)&Qs[r * 64 + dq * 4] = qv;
    }

    float O[4][4], m_i[4], l_i[4];
#pragma unroll
    for (int i = 0; i < 4; i++) {
        m_i[i] = -1e30f; l_i[i] = 0.0f;
#pragma unroll
        for (int j = 0; j < 4; j++) O[i][j] = 0.0f;
    }

    const int kb0 = (qb >= 4) ? (qb - 4) : 0;
    for (int kb = kb0; kb <= qb; kb++) {
        __syncthreads();
#pragma unroll
        for (int t = 0; t < 4; t++) {
            int f = t * 256 + tid;
            int c = f >> 4, dq = f & 15;
            size_t base = (size_t)(kb * 64 + c) * DMODEL + hoff + dq * 4;
            float4 kv = *(const float4*)&k[base];
            Kt[(dq * 4 + 0) * 68 + c] = kv.x;
            Kt[(dq * 4 + 1) * 68 + c] = kv.y;
            Kt[(dq * 4 + 2) * 68 + c] = kv.z;
            Kt[(dq * 4 + 3) * 68 + c] = kv.w;
            *(float4*)&Vs[c * 64 + dq * 4] = *(const float4*)&v[base];
        }
        __syncthreads();

        float S[4][4];
#pragma unroll
        for (int i = 0; i < 4; i++)
#pragma unroll
            for (int j = 0; j < 4; j++) S[i][j] = 0.0f;

#pragma unroll
        for (int d = 0; d < 64; d += 4) {
            float qf[4][4], kf[4][4];
#pragma unroll
            for (int i = 0; i < 4; i++)
                *(float4*)qf[i] = *(const float4*)&Qs[(ty * 4 + i) * 64 + d];
#pragma unroll
            for (int u = 0; u < 4; u++)
                *(float4*)kf[u] = *(const float4*)&Kt[(d + u) * 68 + tx * 4];
#pragma unroll
            for (int i = 0; i < 4; i++)
#pragma unroll
                for (int u = 0; u < 4; u++)
#pragma unroll
                    for (int j = 0; j < 4; j++)
                        S[i][j] = fmaf(qf[i][u], kf[u][j], S[i][j]);
        }

#pragma unroll
        for (int i = 0; i < 4; i++) {
            int qi = qb * 64 + ty * 4 + i;
#pragma unroll
            for (int j = 0; j < 4; j++) {
                int kj = kb * 64 + tx * 4 + j;
                if (kj > qi || (qi - kj) >= WINDOW) S[i][j] = -1e30f;
            }
        }

#pragma unroll
        for (int i = 0; i < 4; i++) {
            float rm = fmaxf(fmaxf(S[i][0], S[i][1]), fmaxf(S[i][2], S[i][3]));
#pragma unroll
            for (int off = 1; off < 16; off <<= 1)
                rm = fmaxf(rm, __shfl_xor_sync(0xffffffffu, rm, off));
            float mnew = fmaxf(m_i[i], rm);
            float alpha = __expf(m_i[i] - mnew);
            float rs = 0.0f;
#pragma unroll
            for (int j = 0; j < 4; j++) { S[i][j] = __expf(S[i][j] - mnew); rs += S[i][j]; }
#pragma unroll
            for (int off = 1; off < 16; off <<= 1)
                rs += __shfl_xor_sync(0xffffffffu, rs, off);
            l_i[i] = l_i[i] * alpha + rs;
            m_i[i] = mnew;
#pragma unroll
            for (int j = 0; j < 4; j++) O[i][j] *= alpha;
        }

#pragma unroll
        for (int i = 0; i < 4; i++)
#pragma unroll
            for (int j = 0; j < 4; j++)
                Ps[(tx * 4 + j) * 68 + ty * 4 + i] = S[i][j];
        __syncthreads();

#pragma unroll
        for (int c = 0; c < 64; c++) {
            float pf[4], vf[4];
            *(float4*)pf = *(const float4*)&Ps[c * 68 + ty * 4];
            *(float4*)vf = *(const float4*)&Vs[c * 64 + tx * 4];
#pragma unroll
            for (int i = 0; i < 4; i++)
#pragma unroll
                for (int j = 0; j < 4; j++)
                    O[i][j] = fmaf(pf[i], vf[j], O[i][j]);
        }
    }

#pragma unroll
    for (int i = 0; i < 4; i++) {
        float inv = 1.0f / l_i[i];
        float4 ov;
        ov.x = O[i][0] * inv; ov.y = O[i][1] * inv;
        ov.z = O[i][2] * inv; ov.w = O[i][3] * inv;
        *(float4*)&o[(size_t)(qb * 64 + ty * 4 + i) * DMODEL + hoff + tx * 4] = ov;
    }
}

// ---------------- launch ----------------
extern "C" void kernel_launch(void* const* d_in, const int* in_sizes, int n_in,
                              void* d_out, int out_size)
{
    // setup_inputs() dict order: 0:x 1:Wq 2:Wk 3:Wv 4:Wo 5:bq 6:bk 7:bv 8:bo
    const float* x  = (const float*)d_in[0];
    const float* Wq = (const float*)d_in[1];
    const float* Wk = (const float*)d_in[2];
    const float* Wv = (const float*)d_in[3];
    const float* Wo = (const float*)d_in[4];
    const float* bq = (const float*)d_in[5];
    const float* bk = (const float*)d_in[6];
    const float* bv = (const float*)d_in[7];
    const float* bo = (const float*)d_in[8];
    float* out = (float*)d_out;

    float *q, *k, *v, *att;
    cudaGetSymbolAddress((void**)&q,   g_q);
    cudaGetSymbolAddress((void**)&k,   g_k);
    cudaGetSymbolAddress((void**)&v,   g_v);
    cudaGetSymbolAddress((void**)&att, g_att);

    const int att_smem = ATT_SMEM_FLOATS * (int)sizeof(float);
    cudaFuncSetAttribute(attn_kernel, cudaFuncAttributeMaxDynamicSharedMemorySize, att_smem);

    dim3 ggrid(DMODEL / 128, SEQ / 128);   // (8, 32)

    gemm_mma<<<ggrid, 256>>>(x, Wq, bq, q);
    gemm_mma<<<ggrid, 256>>>(x, Wk, bk, k);
    gemm_mma<<<ggrid, 256>>>(x, Wv, bv, v);

    dim3 agrid(SEQ / 64, NHEADS);          // (64, 16)
    attn_kernel<<<agrid, 256, att_smem>>>(q, k, v, att);

    gemm_mma<<<ggrid, 256>>>(att, Wo, bo, out);
}

// round 17
// speedup vs baseline: 1.2766x; 1.2766x over previous
#include <cuda_runtime.h>
#include <cuda_bf16.h>
#include <cstdint>

// Problem constants
#define SEQ     4096
#define DMODEL  1024
#define NHEADS  16
#define HD      64
#define WINDOW  256

// ---------------- scratch (no allocation allowed) ----------------
__device__ float g_q[SEQ * DMODEL];
__device__ float g_k[SEQ * DMODEL];
__device__ float g_v[SEQ * DMODEL];
__device__ float g_att[SEQ * DMODEL];
// pre-split planes (bf16 hi/lo)
__device__ __nv_bfloat16 g_xhi[SEQ * DMODEL];
__device__ __nv_bfloat16 g_xlo[SEQ * DMODEL];
__device__ __nv_bfloat16 g_ahi[SEQ * DMODEL];
__device__ __nv_bfloat16 g_alo[SEQ * DMODEL];
// transposed + split weights: [4][DMODEL][DMODEL], n-major ([n][k])
__device__ __nv_bfloat16 g_wthi[4 * DMODEL * DMODEL];
__device__ __nv_bfloat16 g_wtlo[4 * DMODEL * DMODEL];

#define KPAD 40   // halves per smem row (80B)
#define KSW(row, k) ((k) ^ (8 * (((row) >> 3) & 3)))

__device__ __forceinline__ void split_bf(float x, uint16_t& h, uint16_t& l) {
    __nv_bfloat16 hb = __float2bfloat16(x);
    float r = x - __bfloat162float(hb);
    __nv_bfloat16 lb = __float2bfloat16(r);
    h = reinterpret_cast<unsigned short&>(hb);
    l = reinterpret_cast<unsigned short&>(lb);
}

#define MMA_BF16(d, a, b)                                                      \
    asm volatile(                                                              \
        "mma.sync.aligned.m16n8k16.row.col.f32.bf16.bf16.f32 "                 \
        "{%0,%1,%2,%3}, {%4,%5,%6,%7}, {%8,%9}, {%0,%1,%2,%3};"                \
        : "+f"((d)[0]), "+f"((d)[1]), "+f"((d)[2]), "+f"((d)[3])               \
        : "r"((a)[0]), "r"((a)[1]), "r"((a)[2]), "r"((a)[3]),                  \
          "r"((b)[0]), "r"((b)[1]))

#define CP_ASYNC16(dst, src) \
    asm volatile("cp.async.ca.shared.global [%0], [%1], 16;" :: "r"(dst), "l"(src))
#define CP_COMMIT() asm volatile("cp.async.commit_group;" ::: "memory")
#define CP_WAIT(n)  asm volatile("cp.async.wait_group %0;" :: "n"(n) : "memory")

// ---------------- elementwise split: fp32 -> bf16 hi/lo ----------------
__global__ __launch_bounds__(256) void split_kernel(
    const float* __restrict__ in, __nv_bfloat16* __restrict__ hi,
    __nv_bfloat16* __restrict__ lo)
{
    int idx = blockIdx.x * 256 + threadIdx.x;       // float4 index
    float4 v = *(const float4*)&in[(size_t)idx * 4];
    uint16_t h0, l0, h1, l1, h2, l2, h3, l3;
    split_bf(v.x, h0, l0); split_bf(v.y, h1, l1);
    split_bf(v.z, h2, l2); split_bf(v.w, h3, l3);
    uint2 hh, ll;
    hh.x = (uint32_t)h0 | ((uint32_t)h1 << 16);
    hh.y = (uint32_t)h2 | ((uint32_t)h3 << 16);
    ll.x = (uint32_t)l0 | ((uint32_t)l1 << 16);
    ll.y = (uint32_t)l2 | ((uint32_t)l3 << 16);
    *(uint2*)&hi[(size_t)idx * 4] = hh;
    *(uint2*)&lo[(size_t)idx * 4] = ll;
}

// ---------------- transpose + split: W[k][n] -> Wt[n][k] hi/lo ----------------
__global__ __launch_bounds__(256) void tsplit_kernel(
    const float* __restrict__ W, __nv_bfloat16* __restrict__ hi,
    __nv_bfloat16* __restrict__ lo)
{
    __shared__ float t[32][33];
    const int tx = threadIdx.x, ty = threadIdx.y;   // block (32, 8)
    const int k0 = blockIdx.y * 32, n0 = blockIdx.x * 32;
#pragma unroll
    for (int r = 0; r < 4; r++) {
        int row = ty + r * 8;
        t[row][tx] = W[(size_t)(k0 + row) * DMODEL + n0 + tx];
    }
    __syncthreads();
#pragma unroll
    for (int r = 0; r < 4; r++) {
        int a = ty + r * 8;                          // n-offset
        float v = t[tx][a];                          // = W[k0+tx][n0+a]
        uint16_t h, l;
        split_bf(v, h, l);
        size_t o = (size_t)(n0 + a) * DMODEL + k0 + tx;
        reinterpret_cast<uint16_t*>(hi)[o] = h;
        reinterpret_cast<uint16_t*>(lo)[o] = l;
    }
}

// ============ GEMM on pre-split operands, cp.async double-buffered ============
// C[4096,1024] = A @ W + bias; A planes [m][k], B planes [n][k] (pre-transposed).
// 128x128 tile/CTA, 256 threads (8 warps 2x4), K chunks of 32, 2-stage pipeline.
#define PLANE_HALVES (128 * KPAD)
#define SMEM_GEMM_BYTES (2 * 4 * PLANE_HALVES * 2)   // 2 stages x 4 planes = 80KB

__global__ __launch_bounds__(256) void gemm_pre(
    const __nv_bfloat16* __restrict__ Ahi, const __nv_bfloat16* __restrict__ Alo,
    const __nv_bfloat16* __restrict__ Bhi, const __nv_bfloat16* __restrict__ Blo,
    const float* __restrict__ bias, float* __restrict__ C)
{
    extern __shared__ uint16_t smp[];
    const uint32_t sbase = (uint32_t)__cvta_generic_to_shared(smp);

    const int tid  = threadIdx.x;
    const int lane = tid & 31;
    const int wid  = tid >> 5;
    const int mw = (wid >> 2) * 64;
    const int nw = (wid & 3) * 32;
    const int r  = lane >> 2;
    const int cq = (lane & 3) * 2;
    const int m0 = blockIdx.y * 128, n0 = blockIdx.x * 128;

    const uint16_t* srcs[4] = {
        (const uint16_t*)Ahi, (const uint16_t*)Alo,
        (const uint16_t*)Bhi, (const uint16_t*)Blo };
    const int baserow[4] = { m0, m0, n0, n0 };

    // issue one chunk's copies into a stage (8 x 16B per thread)
    auto issue = [&](int ch, int stage) {
#pragma unroll
        for (int p = 0; p < 4; p++) {
#pragma unroll
            for (int i = 0; i < 2; i++) {
                int seg = i * 256 + tid;       // 0..511
                int row = seg >> 2;
                int s4  = seg & 3;             // 16B segment within 64B row
                uint32_t dst = sbase +
                    ((uint32_t)((stage * 4 + p) * PLANE_HALVES + row * KPAD +
                                KSW(row, s4 * 8)) << 1);
                const uint16_t* src = srcs[p] +
                    (size_t)(baserow[p] + row) * DMODEL + ch * 32 + s4 * 8;
                CP_ASYNC16(dst, src);
            }
        }
        CP_COMMIT();
    };

    float acc[4][4][4];
#pragma unroll
    for (int mt = 0; mt < 4; mt++)
#pragma unroll
        for (int nt = 0; nt < 4; nt++)
#pragma unroll
            for (int e = 0; e < 4; e++) acc[mt][nt][e] = 0.0f;

    const int NCH = DMODEL / 32;   // 32 k per chunk
    issue(0, 0);

    for (int ch = 0; ch < NCH; ch++) {
        int cur = ch & 1;
        if (ch + 1 < NCH) { issue(ch + 1, cur ^ 1); CP_WAIT(1); }
        else              { CP_WAIT(0); }
        __syncthreads();

        const uint16_t* Ah = smp + (cur * 4 + 0) * PLANE_HALVES;
        const uint16_t* Al = smp + (cur * 4 + 1) * PLANE_HALVES;
        const uint16_t* Bh = smp + (cur * 4 + 2) * PLANE_HALVES;
        const uint16_t* Bl = smp + (cur * 4 + 3) * PLANE_HALVES;

#pragma unroll
        for (int kk = 0; kk < 32; kk += 16) {
            uint32_t ah[4][4], al[4][4], bh[4][2], bl[4][2];
#pragma unroll
            for (int mt = 0; mt < 4; mt++) {
                int row0 = mw + mt * 16 + r;
                int row1 = row0 + 8;
                int ka0  = row0 * KPAD + KSW(row0, kk + cq);
                int ka0b = row0 * KPAD + KSW(row0, kk + cq + 8);
                int ka1  = row1 * KPAD + KSW(row1, kk + cq);
                int ka1b = row1 * KPAD + KSW(row1, kk + cq + 8);
                ah[mt][0] = *(const uint32_t*)&Ah[ka0];
                ah[mt][1] = *(const uint32_t*)&Ah[ka1];
                ah[mt][2] = *(const uint32_t*)&Ah[ka0b];
                ah[mt][3] = *(const uint32_t*)&Ah[ka1b];
                al[mt][0] = *(const uint32_t*)&Al[ka0];
                al[mt][1] = *(const uint32_t*)&Al[ka1];
                al[mt][2] = *(const uint32_t*)&Al[ka0b];
                al[mt][3] = *(const uint32_t*)&Al[ka1b];
            }
#pragma unroll
            for (int nt = 0; nt < 4; nt++) {
                int n = nw + nt * 8 + r;
                int kb0 = n * KPAD + KSW(n, kk + cq);
                int kb1 = n * KPAD + KSW(n, kk + cq + 8);
                bh[nt][0] = *(const uint32_t*)&Bh[kb0];
                bh[nt][1] = *(const uint32_t*)&Bh[kb1];
                bl[nt][0] = *(const uint32_t*)&Bl[kb0];
                bl[nt][1] = *(const uint32_t*)&Bl[kb1];
            }
#pragma unroll
            for (int mt = 0; mt < 4; mt++)
#pragma unroll
                for (int nt = 0; nt < 4; nt++) {
                    MMA_BF16(acc[mt][nt], ah[mt], bh[nt]);
                    MMA_BF16(acc[mt][nt], ah[mt], bl[nt]);
                    MMA_BF16(acc[mt][nt], al[mt], bh[nt]);
                }
        }
        __syncthreads();
    }

    // ---- epilogue: registers -> C with bias ----
#pragma unroll
    for (int nt = 0; nt < 4; nt++) {
        int col = n0 + nw + nt * 8 + cq;
        float b0 = __ldg(&bias[col]);
        float b1 = __ldg(&bias[col + 1]);
#pragma unroll
        for (int mt = 0; mt < 4; mt++) {
            int row0 = m0 + mw + mt * 16 + r;
            float2 o0 = make_float2(acc[mt][nt][0] + b0, acc[mt][nt][1] + b1);
            float2 o1 = make_float2(acc[mt][nt][2] + b0, acc[mt][nt][3] + b1);
            *(float2*)&C[(size_t)row0 * DMODEL + col] = o0;
            *(float2*)&C[(size_t)(row0 + 8) * DMODEL + col] = o1;
        }
    }
}

// ---------------- sliding-window flash attention (fp32, unchanged) ----------------
#define ATT_SMEM_FLOATS (64*64 + 64*68 + 64*64 + 64*68)

__global__ __launch_bounds__(256) void attn_kernel(
    const float* __restrict__ q, const float* __restrict__ k,
    const float* __restrict__ v, float* __restrict__ o)
{
    extern __shared__ float sm[];
    float* Qs = sm;                 // [64][64]
    float* Kt = Qs + 64 * 64;       // [64][68] d-major
    float* Vs = Kt + 64 * 68;       // [64][64]
    float* Ps = Vs + 64 * 64;       // [64][68] c-major

    const int tid = threadIdx.x;
    const int tx = tid & 15;
    const int ty = tid >> 4;
    const int qb = blockIdx.x;
    const int hoff = blockIdx.y * HD;

#pragma unroll
    for (int t = 0; t < 4; t++) {
        int f = t * 256 + tid;
        int r = f >> 4, dq = f & 15;
        float4 qv = *(const float4*)&q[(size_t)(qb * 64 + r) * DMODEL + hoff + dq * 4];
        qv.x *= 0.125f; qv.y *= 0.125f; qv.z *= 0.125f; qv.w *= 0.125f;
        *(float4*)&Qs[r * 64 + dq * 4] = qv;
    }

    float O[4][4], m_i[4], l_i[4];
#pragma unroll
    for (int i = 0; i < 4; i++) {
        m_i[i] = -1e30f; l_i[i] = 0.0f;
#pragma unroll
        for (int j = 0; j < 4; j++) O[i][j] = 0.0f;
    }

    const int kb0 = (qb >= 4) ? (qb - 4) : 0;
    for (int kb = kb0; kb <= qb; kb++) {
        __syncthreads();
#pragma unroll
        for (int t = 0; t < 4; t++) {
            int f = t * 256 + tid;
            int c = f >> 4, dq = f & 15;
            size_t base = (size_t)(kb * 64 + c) * DMODEL + hoff + dq * 4;
            float4 kv = *(const float4*)&k[base];
            Kt[(dq * 4 + 0) * 68 + c] = kv.x;
            Kt[(dq * 4 + 1) * 68 + c] = kv.y;
            Kt[(dq * 4 + 2) * 68 + c] = kv.z;
            Kt[(dq * 4 + 3) * 68 + c] = kv.w;
            *(float4*)&Vs[c * 64 + dq * 4] = *(const float4*)&v[base];
        }
        __syncthreads();

        float S[4][4];
#pragma unroll
        for (int i = 0; i < 4; i++)
#pragma unroll
            for (int j = 0; j < 4; j++) S[i][j] = 0.0f;

#pragma unroll
        for (int d = 0; d < 64; d += 4) {
            float qf[4][4], kf[4][4];
#pragma unroll
            for (int i = 0; i < 4; i++)
                *(float4*)qf[i] = *(const float4*)&Qs[(ty * 4 + i) * 64 + d];
#pragma unroll
            for (int u = 0; u < 4; u++)
                *(float4*)kf[u] = *(const float4*)&Kt[(d + u) * 68 + tx * 4];
#pragma unroll
            for (int i = 0; i < 4; i++)
#pragma unroll
                for (int u = 0; u < 4; u++)
#pragma unroll
                    for (int j = 0; j < 4; j++)
                        S[i][j] = fmaf(qf[i][u], kf[u][j], S[i][j]);
        }

#pragma unroll
        for (int i = 0; i < 4; i++) {
            int qi = qb * 64 + ty * 4 + i;
#pragma unroll
            for (int j = 0; j < 4; j++) {
                int kj = kb * 64 + tx * 4 + j;
                if (kj > qi || (qi - kj) >= WINDOW) S[i][j] = -1e30f;
            }
        }

#pragma unroll
        for (int i = 0; i < 4; i++) {
            float rm = fmaxf(fmaxf(S[i][0], S[i][1]), fmaxf(S[i][2], S[i][3]));
#pragma unroll
            for (int off = 1; off < 16; off <<= 1)
                rm = fmaxf(rm, __shfl_xor_sync(0xffffffffu, rm, off));
            float mnew = fmaxf(m_i[i], rm);
            float alpha = __expf(m_i[i] - mnew);
            float rs = 0.0f;
#pragma unroll
            for (int j = 0; j < 4; j++) { S[i][j] = __expf(S[i][j] - mnew); rs += S[i][j]; }
#pragma unroll
            for (int off = 1; off < 16; off <<= 1)
                rs += __shfl_xor_sync(0xffffffffu, rs, off);
            l_i[i] = l_i[i] * alpha + rs;
            m_i[i] = mnew;
#pragma unroll
            for (int j = 0; j < 4; j++) O[i][j] *= alpha;
        }

#pragma unroll
        for (int i = 0; i < 4; i++)
#pragma unroll
            for (int j = 0; j < 4; j++)
                Ps[(tx * 4 + j) * 68 + ty * 4 + i] = S[i][j];
        __syncthreads();

#pragma unroll
        for (int c = 0; c < 64; c++) {
            float pf[4], vf[4];
            *(float4*)pf = *(const float4*)&Ps[c * 68 + ty * 4];
            *(float4*)vf = *(const float4*)&Vs[c * 64 + tx * 4];
#pragma unroll
            for (int i = 0; i < 4; i++)
#pragma unroll
                for (int j = 0; j < 4; j++)
                    O[i][j] = fmaf(pf[i], vf[j], O[i][j]);
        }
    }

#pragma unroll
    for (int i = 0; i < 4; i++) {
        float inv = 1.0f / l_i[i];
        float4 ov;
        ov.x = O[i][0] * inv; ov.y = O[i][1] * inv;
        ov.z = O[i][2] * inv; ov.w = O[i][3] * inv;
        *(float4*)&o[(size_t)(qb * 64 + ty * 4 + i) * DMODEL + hoff + tx * 4] = ov;
    }
}

// ---------------- launch ----------------
extern "C" void kernel_launch(void* const* d_in, const int* in_sizes, int n_in,
                              void* d_out, int out_size)
{
    // setup_inputs() dict order: 0:x 1:Wq 2:Wk 3:Wv 4:Wo 5:bq 6:bk 7:bv 8:bo
    const float* x  = (const float*)d_in[0];
    const float* Wq = (const float*)d_in[1];
    const float* Wk = (const float*)d_in[2];
    const float* Wv = (const float*)d_in[3];
    const float* Wo = (const float*)d_in[4];
    const float* bq = (const float*)d_in[5];
    const float* bk = (const float*)d_in[6];
    const float* bv = (const float*)d_in[7];
    const float* bo = (const float*)d_in[8];
    float* out = (float*)d_out;

    float *q, *k, *v, *att;
    __nv_bfloat16 *xhi, *xlo, *ahi, *alo, *wthi, *wtlo;
    cudaGetSymbolAddress((void**)&q,    g_q);
    cudaGetSymbolAddress((void**)&k,    g_k);
    cudaGetSymbolAddress((void**)&v,    g_v);
    cudaGetSymbolAddress((void**)&att,  g_att);
    cudaGetSymbolAddress((void**)&xhi,  g_xhi);
    cudaGetSymbolAddress((void**)&xlo,  g_xlo);
    cudaGetSymbolAddress((void**)&ahi,  g_ahi);
    cudaGetSymbolAddress((void**)&alo,  g_alo);
    cudaGetSymbolAddress((void**)&wthi, g_wthi);
    cudaGetSymbolAddress((void**)&wtlo, g_wtlo);

    const int att_smem = ATT_SMEM_FLOATS * (int)sizeof(float);
    cudaFuncSetAttribute(attn_kernel, cudaFuncAttributeMaxDynamicSharedMemorySize, att_smem);
    cudaFuncSetAttribute(gemm_pre, cudaFuncAttributeMaxDynamicSharedMemorySize, SMEM_GEMM_BYTES);

    const size_t WSZ = (size_t)DMODEL * DMODEL;
    dim3 tgrid(32, 32), tblk(32, 8);
    dim3 ggrid(DMODEL / 128, SEQ / 128);   // (8, 32)

    // pre-split activations and weights
    split_kernel<<<SEQ * DMODEL / 1024, 256>>>(x, xhi, xlo);
    tsplit_kernel<<<tgrid, tblk>>>(Wq, wthi + 0 * WSZ, wtlo + 0 * WSZ);
    tsplit_kernel<<<tgrid, tblk>>>(Wk, wthi + 1 * WSZ, wtlo + 1 * WSZ);
    tsplit_kernel<<<tgrid, tblk>>>(Wv, wthi + 2 * WSZ, wtlo + 2 * WSZ);
    tsplit_kernel<<<tgrid, tblk>>>(Wo, wthi + 3 * WSZ, wtlo + 3 * WSZ);

    gemm_pre<<<ggrid, 256, SMEM_GEMM_BYTES>>>(xhi, xlo, wthi + 0 * WSZ, wtlo + 0 * WSZ, bq, q);
    gemm_pre<<<ggrid, 256, SMEM_GEMM_BYTES>>>(xhi, xlo, wthi + 1 * WSZ, wtlo + 1 * WSZ, bk, k);
    gemm_pre<<<ggrid, 256, SMEM_GEMM_BYTES>>>(xhi, xlo, wthi + 2 * WSZ, wtlo + 2 * WSZ, bv, v);

    dim3 agrid(SEQ / 64, NHEADS);          // (64, 16)
    attn_kernel<<<agrid, 256, att_smem>>>(q, k, v, att);

    split_kernel<<<SEQ * DMODEL / 1024, 256>>>(att, ahi, alo);
    gemm_pre<<<ggrid, 256, SMEM_GEMM_BYTES>>>(ahi, alo, wthi + 3 * WSZ, wtlo + 3 * WSZ, bo, out);
}